// round 15
// baseline (speedup 1.0000x reference)
#include <cuda_runtime.h>
#include <math.h>

#define NN    50000
#define EE    800000
#define ETOT  (EE + NN)
#define C0    192      // IN_DIM(128) + EMB_DIM(64)
#define IND   128
#define EMBD  64
#define HID   128
#define OUTD  64
#define NG    128

#define PART  512
#define NPART ((NN + PART - 1) / PART)   // 98

// ---------------- scratch (device globals; no allocation allowed) ----------------
__device__ float    g_h0[NN * C0];       // normalized x ++ emb lookup
__device__ float    g_act[NN * HID];     // layer activations (GEMM input, layers 2+)
__device__ float    g_H[NN * HID];       // h = act @ W (fp32, gather source)
__device__ float    g_as[NN];
__device__ float    g_ad[NN];
__device__ int      g_deg[NN];
__device__ int      g_indptr[NN + 1];
__device__ int      g_cursor[NN];
__device__ int      g_csr[ETOT];         // src ids grouped by dst
__device__ float    g_pool[NG * HID];
__device__ int      g_flag[NPART];       // chained-scan flags (value = prefix+total+1)

// ---------------- helpers ----------------
__device__ __forceinline__ float lrelu2(float x) { return x > 0.f ? x : 0.2f * x; }
__device__ __forceinline__ float geluf(float v) {
    float t = 0.7978845608028654f * (v + 0.044715f * v * v * v);
    return 0.5f * v * (1.f + tanhf(t));
}
__device__ __forceinline__ void totf32(float v, unsigned& hi, unsigned& lo) {
    asm("cvt.rna.tf32.f32 %0, %1;" : "=r"(hi) : "f"(v));
    float r = v - __uint_as_float(hi);
    asm("cvt.rna.tf32.f32 %0, %1;" : "=r"(lo) : "f"(r));
}
__device__ __forceinline__ void mma8(float* d, const unsigned* a, const unsigned* b) {
    asm volatile(
        "mma.sync.aligned.m16n8k8.row.col.f32.tf32.tf32.f32 "
        "{%0,%1,%2,%3}, {%4,%5,%6,%7}, {%8,%9}, {%0,%1,%2,%3};"
        : "+f"(d[0]), "+f"(d[1]), "+f"(d[2]), "+f"(d[3])
        : "r"(a[0]), "r"(a[1]), "r"(a[2]), "r"(a[3]), "r"(b[0]), "r"(b[1]));
}

// ---------------- kernels ----------------
// warp per node: L2-normalize x row, append embedding. Also zeroes deg/pool/flags
// (safe: this is launch #1; count/scan run later in stream order).
__global__ void prep_kernel(const float* __restrict__ x,
                            const int* __restrict__ node_index,
                            const float* __restrict__ emb) {
    int gtid = blockIdx.x * blockDim.x + threadIdx.x;
    if (gtid < NN) g_deg[gtid] = 0;
    if (gtid < NG * HID) g_pool[gtid] = 0.f;
    if (gtid < NPART) g_flag[gtid] = 0;

    int warp = gtid >> 5;
    int lane = threadIdx.x & 31;
    if (warp >= NN) return;
    float4 v = ((const float4*)(x + (size_t)warp * IND))[lane];
    float ss = v.x * v.x + v.y * v.y + v.z * v.z + v.w * v.w;
    #pragma unroll
    for (int off = 16; off > 0; off >>= 1) ss += __shfl_xor_sync(0xFFFFFFFFu, ss, off);
    float nrm = sqrtf(ss);
    if (nrm == 0.f) nrm = 1e-8f;
    float inv = 1.f / nrm;
    float4 o = make_float4(v.x * inv, v.y * inv, v.z * inv, v.w * inv);
    ((float4*)(g_h0 + (size_t)warp * C0))[lane] = o;
    int vi = node_index[warp];
    if (lane < 16) {
        float4 e = ((const float4*)(emb + (size_t)vi * EMBD))[lane];
        ((float4*)(g_h0 + (size_t)warp * C0 + IND))[lane] = e;
    }
}

__global__ void count_kernel(const int* __restrict__ ei) {
    int e = blockIdx.x * blockDim.x + threadIdx.x;
    if (e >= ETOT) return;
    int d = (e < EE) ? ei[EE + e] : (e - EE);
    atomicAdd(&g_deg[d], 1);
}

// single-kernel chained exclusive scan: 98 blocks (all co-resident on 148 SMs),
// block b spin-waits on block b-1's flag; flag value carries inclusive prefix+1.
__global__ void scanchain_kernel() {
    __shared__ int sd[PART];
    __shared__ int sprefix;
    int b = blockIdx.x, t = threadIdx.x;
    int i = b * PART + t;
    int v = (i < NN) ? g_deg[i] : 0;
    sd[t] = v;
    __syncthreads();
    for (int off = 1; off < PART; off <<= 1) {
        int x = sd[t];
        int add = (t >= off) ? sd[t - off] : 0;
        __syncthreads();
        sd[t] = x + add;
        __syncthreads();
    }
    if (t == 0) {
        int total = sd[PART - 1];
        int prefix = 0;
        if (b > 0) {
            int p;
            while ((p = atomicAdd(&g_flag[b - 1], 0)) == 0) { }
            prefix = p - 1;
        }
        atomicExch(&g_flag[b], prefix + total + 1);
        sprefix = prefix;
    }
    __syncthreads();
    if (i < NN) {
        int incl = sprefix + sd[t];
        g_indptr[i] = incl - v;
        g_cursor[i] = incl - v;
        if (i == NN - 1) g_indptr[NN] = incl;
    }
}

__global__ void scatter_kernel(const int* __restrict__ ei) {
    int e = blockIdx.x * blockDim.x + threadIdx.x;
    if (e >= ETOT) return;
    int s, d;
    if (e < EE) { s = ei[e]; d = ei[EE + e]; }
    else        { s = d = e - EE; }
    int pos = atomicAdd(&g_cursor[d], 1);
    g_csr[pos] = s;
}

// ---- tensor-core GEMM: H = A @ W via split-tf32 mma.sync (fp32 accuracy) ----
// BM=128, BN=128(=HID), BK=8. 256 threads = 8 warps in 4(m)x2(n); warp tile 32x64.
// Fused epilogue: per-row dots with a_s/a_d via shfl + smem atomics.
template <int K>
__global__ __launch_bounds__(256, 1) void gemm_tc_kernel(const float* __restrict__ W,
                                                         const float* __restrict__ a_s,
                                                         const float* __restrict__ a_d) {
    const float* __restrict__ A = (K == C0) ? g_h0 : g_act;
    __shared__ unsigned As_hi[128][9], As_lo[128][9];
    __shared__ unsigned Bs_hi[8][132], Bs_lo[8][132];
    __shared__ float sps[128], spd[128];

    int tid = threadIdx.x;
    int row0 = blockIdx.x * 128;
    int wid = tid >> 5, lane = tid & 31;
    int warp_m = wid & 3, warp_n = wid >> 2;
    int g = lane >> 2, t4 = lane & 3;

    if (tid < 128) { sps[tid] = 0.f; spd[tid] = 0.f; }

    float d[2][8][4];
    #pragma unroll
    for (int mt = 0; mt < 2; mt++)
        #pragma unroll
        for (int nt = 0; nt < 8; nt++)
            #pragma unroll
            for (int j = 0; j < 4; j++) d[mt][nt][j] = 0.f;

    for (int k0 = 0; k0 < K; k0 += 8) {
        {
            int i0 = tid * 4;
            int am = i0 >> 3, ak = i0 & 7;
            int gr = row0 + am;
            float4 av = make_float4(0.f, 0.f, 0.f, 0.f);
            if (gr < NN) av = *(const float4*)&A[(size_t)gr * K + k0 + ak];
            unsigned h, l;
            totf32(av.x, h, l); As_hi[am][ak + 0] = h; As_lo[am][ak + 0] = l;
            totf32(av.y, h, l); As_hi[am][ak + 1] = h; As_lo[am][ak + 1] = l;
            totf32(av.z, h, l); As_hi[am][ak + 2] = h; As_lo[am][ak + 2] = l;
            totf32(av.w, h, l); As_hi[am][ak + 3] = h; As_lo[am][ak + 3] = l;

            int bk = i0 >> 7, bn = i0 & 127;
            float4 bv = *(const float4*)&W[(size_t)(k0 + bk) * HID + bn];
            totf32(bv.x, h, l); Bs_hi[bk][bn + 0] = h; Bs_lo[bk][bn + 0] = l;
            totf32(bv.y, h, l); Bs_hi[bk][bn + 1] = h; Bs_lo[bk][bn + 1] = l;
            totf32(bv.z, h, l); Bs_hi[bk][bn + 2] = h; Bs_lo[bk][bn + 2] = l;
            totf32(bv.w, h, l); Bs_hi[bk][bn + 3] = h; Bs_lo[bk][bn + 3] = l;
        }
        __syncthreads();

        unsigned a_hi[2][4], a_lo[2][4];
        #pragma unroll
        for (int mt = 0; mt < 2; mt++) {
            int m = warp_m * 32 + mt * 16;
            a_hi[mt][0] = As_hi[m + g][t4];         a_lo[mt][0] = As_lo[m + g][t4];
            a_hi[mt][1] = As_hi[m + g + 8][t4];     a_lo[mt][1] = As_lo[m + g + 8][t4];
            a_hi[mt][2] = As_hi[m + g][t4 + 4];     a_lo[mt][2] = As_lo[m + g][t4 + 4];
            a_hi[mt][3] = As_hi[m + g + 8][t4 + 4]; a_lo[mt][3] = As_lo[m + g + 8][t4 + 4];
        }
        #pragma unroll
        for (int nt = 0; nt < 8; nt++) {
            int n = warp_n * 64 + nt * 8 + g;
            unsigned b_hi[2], b_lo[2];
            b_hi[0] = Bs_hi[t4][n];     b_lo[0] = Bs_lo[t4][n];
            b_hi[1] = Bs_hi[t4 + 4][n]; b_lo[1] = Bs_lo[t4 + 4][n];
            #pragma unroll
            for (int mt = 0; mt < 2; mt++) {
                mma8(d[mt][nt], a_hi[mt], b_hi);
                mma8(d[mt][nt], a_hi[mt], b_lo);
                mma8(d[mt][nt], a_lo[mt], b_hi);
            }
        }
        __syncthreads();
    }

    // store H (fp32)
    #pragma unroll
    for (int mt = 0; mt < 2; mt++) {
        int r0 = row0 + warp_m * 32 + mt * 16 + g;
        #pragma unroll
        for (int nt = 0; nt < 8; nt++) {
            int col = warp_n * 64 + nt * 8 + 2 * t4;
            if (r0 < NN)
                *(float2*)&g_H[(size_t)r0 * HID + col] = make_float2(d[mt][nt][0], d[mt][nt][1]);
            if (r0 + 8 < NN)
                *(float2*)&g_H[(size_t)(r0 + 8) * HID + col] = make_float2(d[mt][nt][2], d[mt][nt][3]);
        }
    }

    // fused rowdot: ps/pd per row, reduce over 4 lanes then smem atomics
    float ps[2][2] = {{0.f, 0.f}, {0.f, 0.f}};
    float pd[2][2] = {{0.f, 0.f}, {0.f, 0.f}};
    #pragma unroll
    for (int nt = 0; nt < 8; nt++) {
        int col = warp_n * 64 + nt * 8 + 2 * t4;
        float2 avs = *(const float2*)&a_s[col];
        float2 avd = *(const float2*)&a_d[col];
        #pragma unroll
        for (int mt = 0; mt < 2; mt++) {
            ps[mt][0] += d[mt][nt][0] * avs.x + d[mt][nt][1] * avs.y;
            pd[mt][0] += d[mt][nt][0] * avd.x + d[mt][nt][1] * avd.y;
            ps[mt][1] += d[mt][nt][2] * avs.x + d[mt][nt][3] * avs.y;
            pd[mt][1] += d[mt][nt][2] * avd.x + d[mt][nt][3] * avd.y;
        }
    }
    #pragma unroll
    for (int mt = 0; mt < 2; mt++)
        #pragma unroll
        for (int hhalf = 0; hhalf < 2; hhalf++) {
            float s = ps[mt][hhalf], dd = pd[mt][hhalf];
            s += __shfl_xor_sync(0xFFFFFFFFu, s, 1);
            s += __shfl_xor_sync(0xFFFFFFFFu, s, 2);
            dd += __shfl_xor_sync(0xFFFFFFFFu, dd, 1);
            dd += __shfl_xor_sync(0xFFFFFFFFu, dd, 2);
            if (t4 == 0) {
                int r = warp_m * 32 + mt * 16 + hhalf * 8 + g;
                atomicAdd(&sps[r], s);
                atomicAdd(&spd[r], dd);
            }
        }
    __syncthreads();
    if (tid < 128) {
        int r = row0 + tid;
        if (r < NN) { g_as[r] = sps[tid]; g_ad[r] = spd[tid]; }
    }
}

// warp per dst node: online-softmax aggregation (R12 proven form, fp32 H)
__global__ void aggregate_kernel(const float* __restrict__ bias) {
    int warp = (blockIdx.x * blockDim.x + threadIdx.x) >> 5;
    int lane = threadIdx.x & 31;
    if (warp >= NN) return;
    int start = g_indptr[warp], end = g_indptr[warp + 1];
    float adv = g_ad[warp];
    float m = -3.0e38f, sum = 0.f;
    float4 acc = make_float4(0.f, 0.f, 0.f, 0.f);

    int s = g_csr[start];            // every node has a self-loop -> end > start
    float asv = g_as[s];
    for (int j = start; j < end; j++) {
        int jn = j + 1;
        int s2 = (jn < end) ? g_csr[jn] : s;
        float as2 = g_as[s2];
        float4 h = ((const float4*)g_H)[(size_t)s * 32 + lane];

        float l = lrelu2(asv + adv);
        float mn = fmaxf(m, l);
        float r = __expf(m - mn);
        float w = __expf(l - mn);
        m = mn;
        sum = sum * r + w;
        acc.x = acc.x * r + w * h.x;
        acc.y = acc.y * r + w * h.y;
        acc.z = acc.z * r + w * h.z;
        acc.w = acc.w * r + w * h.w;

        s = s2; asv = as2;
    }
    float inv = 1.f / sum;
    float4 b = ((const float4*)bias)[lane];
    float4 o;
    o.x = geluf(acc.x * inv + b.x);
    o.y = geluf(acc.y * inv + b.y);
    o.z = geluf(acc.z * inv + b.z);
    o.w = geluf(acc.w * inv + b.w);
    ((float4*)g_act)[(size_t)warp * 32 + lane] = o;
}

// global_add_pool
__global__ void pool_kernel(const int* __restrict__ batch) {
    int n0 = blockIdx.x * 128;
    int c = threadIdx.x;
    if (n0 >= NN) return;
    int cur = batch[n0];
    float acc = 0.f;
    for (int i = 0; i < 128; i++) {
        int n = n0 + i;
        if (n >= NN) break;
        int b = batch[n];
        if (b != cur) {
            atomicAdd(&g_pool[cur * HID + c], acc);
            acc = 0.f;
            cur = b;
        }
        acc += g_act[(size_t)n * HID + c];
    }
    atomicAdd(&g_pool[cur * HID + c], acc);
}

__global__ void final_kernel(const float* __restrict__ fcW,
                             const float* __restrict__ fcb,
                             float* __restrict__ out) {
    __shared__ float gr[HID];
    int g = blockIdx.x, c = threadIdx.x;   // 64 threads
    gr[c] = g_pool[g * HID + c];
    gr[c + 64] = g_pool[g * HID + c + 64];
    __syncthreads();
    float acc = fcb[c];
    #pragma unroll
    for (int k = 0; k < HID; k++) acc += gr[k] * fcW[k * OUTD + c];
    float v = acc > 0.f ? acc : 0.01f * acc;
    out[g * OUTD + c] = v;
}

// ---------------- launch ----------------
// Order chosen so launch #4 = gemm_tc_kernel<C0> (the ncu window profiles launch #4).
extern "C" void kernel_launch(void* const* d_in, const int* in_sizes, int n_in,
                              void* d_out, int out_size) {
    const float* x          = (const float*)d_in[0];
    const int*   node_index = (const int*)  d_in[1];
    const int*   edge_index = (const int*)  d_in[2];
    const int*   batch      = (const int*)  d_in[3];
    const float* emb        = (const float*)d_in[4];
    const float* W1  = (const float*)d_in[5];
    const float* a1s = (const float*)d_in[6];
    const float* a1d = (const float*)d_in[7];
    const float* b1  = (const float*)d_in[8];
    const float* W2  = (const float*)d_in[9];
    const float* a2s = (const float*)d_in[10];
    const float* a2d = (const float*)d_in[11];
    const float* b2  = (const float*)d_in[12];
    const float* W3  = (const float*)d_in[13];
    const float* a3s = (const float*)d_in[14];
    const float* a3d = (const float*)d_in[15];
    const float* b3  = (const float*)d_in[16];
    const float* fcW = (const float*)d_in[17];
    const float* fcb = (const float*)d_in[18];
    float* out = (float*)d_out;

    const int gWarp = (NN + 7) / 8;
    const int gEdge = (ETOT + 255) / 256;
    const int gGemm = (NN + 127) / 128;    // 391

    prep_kernel<<<gWarp, 256>>>(x, node_index, emb);      // #1 (also zeroes deg/pool/flags)
    count_kernel<<<gEdge, 256>>>(edge_index);             // #2
    scanchain_kernel<<<NPART, PART>>>();                  // #3 (fused 3-phase scan)
    gemm_tc_kernel<C0><<<gGemm, 256>>>(W1, a1s, a1d);     // #4  <-- profiled by ncu window
    scatter_kernel<<<gEdge, 256>>>(edge_index);           // #5
    aggregate_kernel<<<gWarp, 256>>>(b1);                 // #6

    gemm_tc_kernel<HID><<<gGemm, 256>>>(W2, a2s, a2d);    // #7
    aggregate_kernel<<<gWarp, 256>>>(b2);                 // #8

    gemm_tc_kernel<HID><<<gGemm, 256>>>(W3, a3s, a3d);    // #9
    aggregate_kernel<<<gWarp, 256>>>(b3);                 // #10

    pool_kernel<<<(NN + 127) / 128, 128>>>(batch);        // #11
    final_kernel<<<NG, OUTD>>>(fcW, fcb, out);            // #12
}

// round 16
// speedup vs baseline: 1.1940x; 1.1940x over previous
#include <cuda_runtime.h>
#include <math.h>

#define NN    50000
#define EE    800000
#define ETOT  (EE + NN)
#define C0    192      // IN_DIM(128) + EMB_DIM(64)
#define IND   128
#define EMBD  64
#define HID   128
#define OUTD  64
#define NG    128

#define PART  512
#define NPART ((NN + PART - 1) / PART)   // 98

// ---------------- scratch (device globals; no allocation allowed) ----------------
__device__ float    g_h0[NN * C0];       // normalized x ++ emb lookup
__device__ float    g_act[NN * HID];     // layer activations (GEMM input, layers 2+)
__device__ float    g_H[NN * HID];       // h = act @ W (fp32, gather source)
__device__ float    g_as[NN];
__device__ float    g_ad[NN];
__device__ int      g_deg[NN];
__device__ int      g_indptr[NN + 1];
__device__ int      g_cursor[NN];
__device__ int      g_csr[ETOT];         // src ids grouped by dst
__device__ float    g_pool[NG * HID];
__device__ int      g_bsum[NPART];
__device__ int      g_boff[NPART];

// ---------------- helpers ----------------
__device__ __forceinline__ float lrelu2(float x) { return x > 0.f ? x : 0.2f * x; }
__device__ __forceinline__ float geluf(float v) {
    float t = 0.7978845608028654f * (v + 0.044715f * v * v * v);
    return 0.5f * v * (1.f + tanhf(t));
}
__device__ __forceinline__ void totf32(float v, unsigned& hi, unsigned& lo) {
    asm("cvt.rna.tf32.f32 %0, %1;" : "=r"(hi) : "f"(v));
    float r = v - __uint_as_float(hi);
    asm("cvt.rna.tf32.f32 %0, %1;" : "=r"(lo) : "f"(r));
}
__device__ __forceinline__ void mma8(float* d, const unsigned* a, const unsigned* b) {
    asm volatile(
        "mma.sync.aligned.m16n8k8.row.col.f32.tf32.tf32.f32 "
        "{%0,%1,%2,%3}, {%4,%5,%6,%7}, {%8,%9}, {%0,%1,%2,%3};"
        : "+f"(d[0]), "+f"(d[1]), "+f"(d[2]), "+f"(d[3])
        : "r"(a[0]), "r"(a[1]), "r"(a[2]), "r"(a[3]), "r"(b[0]), "r"(b[1]));
}

// ---------------- kernels ----------------
// warp per node: L2-normalize x row, append embedding. Also zeroes deg/pool.
__global__ void prep_kernel(const float* __restrict__ x,
                            const int* __restrict__ node_index,
                            const float* __restrict__ emb) {
    int gtid = blockIdx.x * blockDim.x + threadIdx.x;
    if (gtid < NN) g_deg[gtid] = 0;
    if (gtid < NG * HID) g_pool[gtid] = 0.f;

    int warp = gtid >> 5;
    int lane = threadIdx.x & 31;
    if (warp >= NN) return;
    float4 v = ((const float4*)(x + (size_t)warp * IND))[lane];
    float ss = v.x * v.x + v.y * v.y + v.z * v.z + v.w * v.w;
    #pragma unroll
    for (int off = 16; off > 0; off >>= 1) ss += __shfl_xor_sync(0xFFFFFFFFu, ss, off);
    float nrm = sqrtf(ss);
    if (nrm == 0.f) nrm = 1e-8f;
    float inv = 1.f / nrm;
    float4 o = make_float4(v.x * inv, v.y * inv, v.z * inv, v.w * inv);
    ((float4*)(g_h0 + (size_t)warp * C0))[lane] = o;
    int vi = node_index[warp];
    if (lane < 16) {
        float4 e = ((const float4*)(emb + (size_t)vi * EMBD))[lane];
        ((float4*)(g_h0 + (size_t)warp * C0 + IND))[lane] = e;
    }
}

__global__ void count_kernel(const int* __restrict__ ei) {
    int e = blockIdx.x * blockDim.x + threadIdx.x;
    if (e >= ETOT) return;
    int d = (e < EE) ? ei[EE + e] : (e - EE);
    atomicAdd(&g_deg[d], 1);
}

// ---- parallel 3-phase exclusive scan of g_deg -> g_indptr / g_cursor ----
__global__ void blocksum_kernel() {
    __shared__ int sd[PART];
    int i = blockIdx.x * PART + threadIdx.x;
    sd[threadIdx.x] = (i < NN) ? g_deg[i] : 0;
    __syncthreads();
    #pragma unroll
    for (int off = PART / 2; off > 0; off >>= 1) {
        if (threadIdx.x < off) sd[threadIdx.x] += sd[threadIdx.x + off];
        __syncthreads();
    }
    if (threadIdx.x == 0) g_bsum[blockIdx.x] = sd[0];
}

__global__ void partscan_kernel() {   // 1 block, 128 threads, NPART<=128
    __shared__ int sd[128];
    int t = threadIdx.x;
    int v = (t < NPART) ? g_bsum[t] : 0;
    sd[t] = v;
    __syncthreads();
    for (int off = 1; off < 128; off <<= 1) {
        int x = sd[t];
        int add = (t >= off) ? sd[t - off] : 0;
        __syncthreads();
        sd[t] = x + add;
        __syncthreads();
    }
    if (t < NPART) g_boff[t] = sd[t] - v;   // exclusive
}

__global__ void localscan_kernel() {
    __shared__ int sd[PART];
    int b = blockIdx.x;
    int i = b * PART + threadIdx.x;
    int v = (i < NN) ? g_deg[i] : 0;
    sd[threadIdx.x] = v;
    __syncthreads();
    for (int off = 1; off < PART; off <<= 1) {
        int x = sd[threadIdx.x];
        int add = (threadIdx.x >= (unsigned)off) ? sd[threadIdx.x - off] : 0;
        __syncthreads();
        sd[threadIdx.x] = x + add;
        __syncthreads();
    }
    if (i < NN) {
        int incl = g_boff[b] + sd[threadIdx.x];
        g_indptr[i] = incl - v;
        g_cursor[i] = incl - v;
        if (i == NN - 1) g_indptr[NN] = incl;
    }
}

__global__ void scatter_kernel(const int* __restrict__ ei) {
    int e = blockIdx.x * blockDim.x + threadIdx.x;
    if (e >= ETOT) return;
    int s, d;
    if (e < EE) { s = ei[e]; d = ei[EE + e]; }
    else        { s = d = e - EE; }
    int pos = atomicAdd(&g_cursor[d], 1);
    g_csr[pos] = s;
}

// ---- pipelined tensor-core GEMM: H = A @ W via split-tf32 mma.sync ----
// BM=128, BN=128(=HID), BK=8, double-buffered smem, one sync per k-step.
// 256 threads = 8 warps 4(m)x2(n); warp tile 32x64. Fused rowdot epilogue.
template <int K>
__global__ __launch_bounds__(256, 2) void gemm_tc_kernel(const float* __restrict__ W,
                                                         const float* __restrict__ a_s,
                                                         const float* __restrict__ a_d) {
    const float* __restrict__ A = (K == C0) ? g_h0 : g_act;
    constexpr int KT = K / 8;
    __shared__ unsigned As_hi[2][128][9], As_lo[2][128][9];
    __shared__ unsigned Bs_hi[2][8][132], Bs_lo[2][8][132];
    __shared__ float sps[128], spd[128];

    int tid = threadIdx.x;
    int row0 = blockIdx.x * 128;
    int wid = tid >> 5, lane = tid & 31;
    int warp_m = wid & 3, warp_n = wid >> 2;
    int g = lane >> 2, t4 = lane & 3;

    if (tid < 128) { sps[tid] = 0.f; spd[tid] = 0.f; }

    // loader indices (thread -> 4 contiguous elements)
    int i0 = tid * 4;
    int am = i0 >> 3, ak = i0 & 7;          // A: row am, cols ak..ak+3
    int bk = i0 >> 7, bn = i0 & 127;        // B: row bk, cols bn..bn+3
    int agr = row0 + am;
    bool aok = (agr < NN);
    const float* Aptr = A + (size_t)agr * K + ak;

    float d[2][8][4];
    #pragma unroll
    for (int mt = 0; mt < 2; mt++)
        #pragma unroll
        for (int nt = 0; nt < 8; nt++)
            #pragma unroll
            for (int j = 0; j < 4; j++) d[mt][nt][j] = 0.f;

    // prologue: load + convert + store k-step 0 into buffer 0
    {
        float4 av = make_float4(0.f, 0.f, 0.f, 0.f);
        if (aok) av = *(const float4*)Aptr;
        float4 bv = *(const float4*)&W[(size_t)bk * HID + bn];
        unsigned h, l;
        totf32(av.x, h, l); As_hi[0][am][ak + 0] = h; As_lo[0][am][ak + 0] = l;
        totf32(av.y, h, l); As_hi[0][am][ak + 1] = h; As_lo[0][am][ak + 1] = l;
        totf32(av.z, h, l); As_hi[0][am][ak + 2] = h; As_lo[0][am][ak + 2] = l;
        totf32(av.w, h, l); As_hi[0][am][ak + 3] = h; As_lo[0][am][ak + 3] = l;
        totf32(bv.x, h, l); Bs_hi[0][bk][bn + 0] = h; Bs_lo[0][bk][bn + 0] = l;
        totf32(bv.y, h, l); Bs_hi[0][bk][bn + 1] = h; Bs_lo[0][bk][bn + 1] = l;
        totf32(bv.z, h, l); Bs_hi[0][bk][bn + 2] = h; Bs_lo[0][bk][bn + 2] = l;
        totf32(bv.w, h, l); Bs_hi[0][bk][bn + 3] = h; Bs_lo[0][bk][bn + 3] = l;
    }
    __syncthreads();

    for (int kt = 0; kt < KT; kt++) {
        int cur = kt & 1, nxt = cur ^ 1;

        // issue next tile's global loads FIRST (latency overlapped with MMAs)
        float4 aN, bN;
        bool more = (kt + 1 < KT);
        if (more) {
            int k0n = (kt + 1) * 8;
            aN = make_float4(0.f, 0.f, 0.f, 0.f);
            if (aok) aN = *(const float4*)(Aptr + k0n);
            bN = *(const float4*)&W[(size_t)(k0n + bk) * HID + bn];
        }

        // fragments + MMAs from current buffer
        unsigned a_hi[2][4], a_lo[2][4];
        #pragma unroll
        for (int mt = 0; mt < 2; mt++) {
            int m = warp_m * 32 + mt * 16;
            a_hi[mt][0] = As_hi[cur][m + g][t4];         a_lo[mt][0] = As_lo[cur][m + g][t4];
            a_hi[mt][1] = As_hi[cur][m + g + 8][t4];     a_lo[mt][1] = As_lo[cur][m + g + 8][t4];
            a_hi[mt][2] = As_hi[cur][m + g][t4 + 4];     a_lo[mt][2] = As_lo[cur][m + g][t4 + 4];
            a_hi[mt][3] = As_hi[cur][m + g + 8][t4 + 4]; a_lo[mt][3] = As_lo[cur][m + g + 8][t4 + 4];
        }
        #pragma unroll
        for (int nt = 0; nt < 8; nt++) {
            int n = warp_n * 64 + nt * 8 + g;
            unsigned b_hi[2], b_lo[2];
            b_hi[0] = Bs_hi[cur][t4][n];     b_lo[0] = Bs_lo[cur][t4][n];
            b_hi[1] = Bs_hi[cur][t4 + 4][n]; b_lo[1] = Bs_lo[cur][t4 + 4][n];
            #pragma unroll
            for (int mt = 0; mt < 2; mt++) {
                mma8(d[mt][nt], a_hi[mt], b_hi);
                mma8(d[mt][nt], a_hi[mt], b_lo);
                mma8(d[mt][nt], a_lo[mt], b_hi);
            }
        }

        // convert + store next tile into the other buffer
        if (more) {
            unsigned h, l;
            totf32(aN.x, h, l); As_hi[nxt][am][ak + 0] = h; As_lo[nxt][am][ak + 0] = l;
            totf32(aN.y, h, l); As_hi[nxt][am][ak + 1] = h; As_lo[nxt][am][ak + 1] = l;
            totf32(aN.z, h, l); As_hi[nxt][am][ak + 2] = h; As_lo[nxt][am][ak + 2] = l;
            totf32(aN.w, h, l); As_hi[nxt][am][ak + 3] = h; As_lo[nxt][am][ak + 3] = l;
            totf32(bN.x, h, l); Bs_hi[nxt][bk][bn + 0] = h; Bs_lo[nxt][bk][bn + 0] = l;
            totf32(bN.y, h, l); Bs_hi[nxt][bk][bn + 1] = h; Bs_lo[nxt][bk][bn + 1] = l;
            totf32(bN.z, h, l); Bs_hi[nxt][bk][bn + 2] = h; Bs_lo[nxt][bk][bn + 2] = l;
            totf32(bN.w, h, l); Bs_hi[nxt][bk][bn + 3] = h; Bs_lo[nxt][bk][bn + 3] = l;
        }
        __syncthreads();
    }

    // store H (fp32)
    #pragma unroll
    for (int mt = 0; mt < 2; mt++) {
        int r0 = row0 + warp_m * 32 + mt * 16 + g;
        #pragma unroll
        for (int nt = 0; nt < 8; nt++) {
            int col = warp_n * 64 + nt * 8 + 2 * t4;
            if (r0 < NN)
                *(float2*)&g_H[(size_t)r0 * HID + col] = make_float2(d[mt][nt][0], d[mt][nt][1]);
            if (r0 + 8 < NN)
                *(float2*)&g_H[(size_t)(r0 + 8) * HID + col] = make_float2(d[mt][nt][2], d[mt][nt][3]);
        }
    }

    // fused rowdot: ps/pd per row, reduce over 4 lanes then smem atomics
    float ps[2][2] = {{0.f, 0.f}, {0.f, 0.f}};
    float pd[2][2] = {{0.f, 0.f}, {0.f, 0.f}};
    #pragma unroll
    for (int nt = 0; nt < 8; nt++) {
        int col = warp_n * 64 + nt * 8 + 2 * t4;
        float2 avs = *(const float2*)&a_s[col];
        float2 avd = *(const float2*)&a_d[col];
        #pragma unroll
        for (int mt = 0; mt < 2; mt++) {
            ps[mt][0] += d[mt][nt][0] * avs.x + d[mt][nt][1] * avs.y;
            pd[mt][0] += d[mt][nt][0] * avd.x + d[mt][nt][1] * avd.y;
            ps[mt][1] += d[mt][nt][2] * avs.x + d[mt][nt][3] * avs.y;
            pd[mt][1] += d[mt][nt][2] * avd.x + d[mt][nt][3] * avd.y;
        }
    }
    #pragma unroll
    for (int mt = 0; mt < 2; mt++)
        #pragma unroll
        for (int hhalf = 0; hhalf < 2; hhalf++) {
            float s = ps[mt][hhalf], dd = pd[mt][hhalf];
            s += __shfl_xor_sync(0xFFFFFFFFu, s, 1);
            s += __shfl_xor_sync(0xFFFFFFFFu, s, 2);
            dd += __shfl_xor_sync(0xFFFFFFFFu, dd, 1);
            dd += __shfl_xor_sync(0xFFFFFFFFu, dd, 2);
            if (t4 == 0) {
                int r = warp_m * 32 + mt * 16 + hhalf * 8 + g;
                atomicAdd(&sps[r], s);
                atomicAdd(&spd[r], dd);
            }
        }
    __syncthreads();
    if (tid < 128) {
        int r = row0 + tid;
        if (r < NN) { g_as[r] = sps[tid]; g_ad[r] = spd[tid]; }
    }
}

// warp per dst node: online-softmax aggregation (R12 proven form, fp32 H)
__global__ void aggregate_kernel(const float* __restrict__ bias) {
    int warp = (blockIdx.x * blockDim.x + threadIdx.x) >> 5;
    int lane = threadIdx.x & 31;
    if (warp >= NN) return;
    int start = g_indptr[warp], end = g_indptr[warp + 1];
    float adv = g_ad[warp];
    float m = -3.0e38f, sum = 0.f;
    float4 acc = make_float4(0.f, 0.f, 0.f, 0.f);

    int s = g_csr[start];            // every node has a self-loop -> end > start
    float asv = g_as[s];
    for (int j = start; j < end; j++) {
        int jn = j + 1;
        int s2 = (jn < end) ? g_csr[jn] : s;
        float as2 = g_as[s2];
        float4 h = ((const float4*)g_H)[(size_t)s * 32 + lane];

        float l = lrelu2(asv + adv);
        float mn = fmaxf(m, l);
        float r = __expf(m - mn);
        float w = __expf(l - mn);
        m = mn;
        sum = sum * r + w;
        acc.x = acc.x * r + w * h.x;
        acc.y = acc.y * r + w * h.y;
        acc.z = acc.z * r + w * h.z;
        acc.w = acc.w * r + w * h.w;

        s = s2; asv = as2;
    }
    float inv = 1.f / sum;
    float4 b = ((const float4*)bias)[lane];
    float4 o;
    o.x = geluf(acc.x * inv + b.x);
    o.y = geluf(acc.y * inv + b.y);
    o.z = geluf(acc.z * inv + b.z);
    o.w = geluf(acc.w * inv + b.w);
    ((float4*)g_act)[(size_t)warp * 32 + lane] = o;
}

// global_add_pool
__global__ void pool_kernel(const int* __restrict__ batch) {
    int n0 = blockIdx.x * 128;
    int c = threadIdx.x;
    if (n0 >= NN) return;
    int cur = batch[n0];
    float acc = 0.f;
    for (int i = 0; i < 128; i++) {
        int n = n0 + i;
        if (n >= NN) break;
        int b = batch[n];
        if (b != cur) {
            atomicAdd(&g_pool[cur * HID + c], acc);
            acc = 0.f;
            cur = b;
        }
        acc += g_act[(size_t)n * HID + c];
    }
    atomicAdd(&g_pool[cur * HID + c], acc);
}

__global__ void final_kernel(const float* __restrict__ fcW,
                             const float* __restrict__ fcb,
                             float* __restrict__ out) {
    __shared__ float gr[HID];
    int g = blockIdx.x, c = threadIdx.x;   // 64 threads
    gr[c] = g_pool[g * HID + c];
    gr[c + 64] = g_pool[g * HID + c + 64];
    __syncthreads();
    float acc = fcb[c];
    #pragma unroll
    for (int k = 0; k < HID; k++) acc += gr[k] * fcW[k * OUTD + c];
    float v = acc > 0.f ? acc : 0.01f * acc;
    out[g * OUTD + c] = v;
}

// ---------------- launch ----------------
// Launch #4 = gemm_tc_kernel<C0> (the ncu window profiles launch #4).
extern "C" void kernel_launch(void* const* d_in, const int* in_sizes, int n_in,
                              void* d_out, int out_size) {
    const float* x          = (const float*)d_in[0];
    const int*   node_index = (const int*)  d_in[1];
    const int*   edge_index = (const int*)  d_in[2];
    const int*   batch      = (const int*)  d_in[3];
    const float* emb        = (const float*)d_in[4];
    const float* W1  = (const float*)d_in[5];
    const float* a1s = (const float*)d_in[6];
    const float* a1d = (const float*)d_in[7];
    const float* b1  = (const float*)d_in[8];
    const float* W2  = (const float*)d_in[9];
    const float* a2s = (const float*)d_in[10];
    const float* a2d = (const float*)d_in[11];
    const float* b2  = (const float*)d_in[12];
    const float* W3  = (const float*)d_in[13];
    const float* a3s = (const float*)d_in[14];
    const float* a3d = (const float*)d_in[15];
    const float* b3  = (const float*)d_in[16];
    const float* fcW = (const float*)d_in[17];
    const float* fcb = (const float*)d_in[18];
    float* out = (float*)d_out;

    const int gWarp = (NN + 7) / 8;
    const int gEdge = (ETOT + 255) / 256;
    const int gGemm = (NN + 127) / 128;    // 391

    prep_kernel<<<gWarp, 256>>>(x, node_index, emb);      // #1 (also zeroes deg/pool)
    count_kernel<<<gEdge, 256>>>(edge_index);             // #2
    blocksum_kernel<<<NPART, PART>>>();                   // #3
    gemm_tc_kernel<C0><<<gGemm, 256>>>(W1, a1s, a1d);     // #4  <-- profiled
    partscan_kernel<<<1, 128>>>();                        // #5
    localscan_kernel<<<NPART, PART>>>();                  // #6
    scatter_kernel<<<gEdge, 256>>>(edge_index);           // #7
    aggregate_kernel<<<gWarp, 256>>>(b1);                 // #8

    gemm_tc_kernel<HID><<<gGemm, 256>>>(W2, a2s, a2d);    // #9
    aggregate_kernel<<<gWarp, 256>>>(b2);                 // #10

    gemm_tc_kernel<HID><<<gGemm, 256>>>(W3, a3s, a3d);    // #11
    aggregate_kernel<<<gWarp, 256>>>(b3);                 // #12

    pool_kernel<<<(NN + 127) / 128, 128>>>(batch);        // #13
    final_kernel<<<NG, OUTD>>>(fcW, fcb, out);            // #14
}